// round 7
// baseline (speedup 1.0000x reference)
#include <cuda_runtime.h>
#include <math.h>

#define B   8
#define N1  32768
#define NP1 512
#define NS1 32
#define N2  512
#define NP2 256
#define NS2 64
#define CAP 128

typedef unsigned long long ull;

// ---------------- scratch (device globals; no allocations) ----------------
__device__ float g_w1t [6  * 64 ];
__device__ float g_w2t [64 * 64 ];
__device__ float g_w3t [64 * 128];
__device__ float g_w1t2[131 * 128];
__device__ float g_w2t2[128 * 128];
__device__ float g_w3t2[128 * 285];

__device__ float g_norms1[B * N1];
__device__ int   g_fps1 [B * NP1];
__device__ float g_nx1  [B * NP1 * 3];
__device__ int   g_cnt1 [B * NP1];
__device__ int   g_list1[B * NP1 * 64];
__device__ float g_feat1[B * NP1 * 128];

__device__ float g_norms2[B * N2];
__device__ int   g_fps2 [B * NP2];
__device__ float g_nx2  [B * NP2 * 3];
__device__ int   g_cnt2 [B * NP2];
__device__ int   g_list2[B * NP2 * 64];

// ---------------- weight transpose: W[o][c] -> Wt[c][o] --------------------
__global__ void k_transpose_all(const float* __restrict__ w1, const float* __restrict__ w2,
                                const float* __restrict__ w3, const float* __restrict__ u1,
                                const float* __restrict__ u2, const float* __restrict__ u3) {
    int i = blockIdx.x * 256 + threadIdx.x;
    if (i < 384) {                              // 64x6
        int o = i / 6, c = i % 6;               g_w1t [c * 64  + o] = w1[i];
    } else if (i < 4480) {                      // 64x64
        int j = i - 384;  int o = j / 64,  c = j % 64;  g_w2t [c * 64  + o] = w2[j];
    } else if (i < 12672) {                     // 128x64
        int j = i - 4480; int o = j / 64,  c = j % 64;  g_w3t [c * 128 + o] = w3[j];
    } else if (i < 29440) {                     // 128x131
        int j = i - 12672;int o = j / 131, c = j % 131; g_w1t2[c * 128 + o] = u1[j];
    } else if (i < 45824) {                     // 128x128
        int j = i - 29440;int o = j / 128, c = j % 128; g_w2t2[c * 128 + o] = u2[j];
    } else if (i < 82304) {                     // 285x128
        int j = i - 45824;int o = j / 128, c = j % 128; g_w3t2[c * 285 + o] = u3[j];
    }
}

// ---------------- squared norms --------------------------------------------
__global__ void k_norms1(const float* __restrict__ xyz) {
    int i = blockIdx.x * 256 + threadIdx.x;
    if (i < B * N1) {
        int b = i >> 15, n = i & (N1 - 1);
        const float* base = xyz + (size_t)b * 6 * N1;
        float x = base[n], y = base[N1 + n], z = base[2 * N1 + n];
        g_norms1[i] = (x * x + y * y) + z * z;
    }
}

__global__ void k_norms2() {
    int i = blockIdx.x * 256 + threadIdx.x;
    if (i < B * N2) {
        float x = g_nx1[i * 3], y = g_nx1[i * 3 + 1], z = g_nx1[i * 3 + 2];
        g_norms2[i] = (x * x + y * y) + z * z;
    }
}

// ---------------- FPS stage 1: 32768 -> 512 (one CTA per batch) ------------
__global__ void __launch_bounds__(512, 1) k_fps1(const float* __restrict__ xyz) {
    int b = blockIdx.x, tid = threadIdx.x;
    const float*  X  = xyz + (size_t)b * 6 * N1;
    const float*  Y  = X + N1;
    const float*  Z  = X + 2 * N1;
    const float4* X4 = (const float4*)X;
    const float4* Y4 = (const float4*)Y;
    const float4* Z4 = (const float4*)Z;

    __shared__ ull s_wmax[16];
    __shared__ ull s_bkey;

    float dist[64];
#pragma unroll
    for (int i = 0; i < 64; ++i) dist[i] = 1e10f;

    unsigned far = 0;
    float cx = X[0], cy = Y[0], cz = Z[0];

    for (int it = 0; it < NP1; ++it) {
        if (tid == 0) {
            g_fps1[b * NP1 + it] = (int)far;
            g_nx1[(b * NP1 + it) * 3 + 0] = cx;
            g_nx1[(b * NP1 + it) * 3 + 1] = cy;
            g_nx1[(b * NP1 + it) * 3 + 2] = cz;
        }
        float bv = -1.0f; unsigned bi = 0;
#pragma unroll
        for (int j = 0; j < 16; ++j) {
            int f4 = j * 512 + tid;
            float4 xv = X4[f4], yv = Y4[f4], zv = Z4[f4];
            float dx, dy, dz, d, nd;
            dx = xv.x - cx; dy = yv.x - cy; dz = zv.x - cz; d = dx * dx + dy * dy + dz * dz;
            nd = fminf(dist[4 * j + 0], d); dist[4 * j + 0] = nd;
            if (nd > bv) { bv = nd; bi = (unsigned)(4 * f4 + 0); }
            dx = xv.y - cx; dy = yv.y - cy; dz = zv.y - cz; d = dx * dx + dy * dy + dz * dz;
            nd = fminf(dist[4 * j + 1], d); dist[4 * j + 1] = nd;
            if (nd > bv) { bv = nd; bi = (unsigned)(4 * f4 + 1); }
            dx = xv.z - cx; dy = yv.z - cy; dz = zv.z - cz; d = dx * dx + dy * dy + dz * dz;
            nd = fminf(dist[4 * j + 2], d); dist[4 * j + 2] = nd;
            if (nd > bv) { bv = nd; bi = (unsigned)(4 * f4 + 2); }
            dx = xv.w - cx; dy = yv.w - cy; dz = zv.w - cz; d = dx * dx + dy * dy + dz * dz;
            nd = fminf(dist[4 * j + 3], d); dist[4 * j + 3] = nd;
            if (nd > bv) { bv = nd; bi = (unsigned)(4 * f4 + 3); }
        }
        // pack (value, ~idx): u64 max => max value, smallest index on ties
        ull key = ((ull)__float_as_uint(bv) << 32) | (ull)(0xFFFFFFFFu - bi);
#pragma unroll
        for (int o = 16; o; o >>= 1) {
            ull k2 = __shfl_xor_sync(0xFFFFFFFFu, key, o);
            if (k2 > key) key = k2;
        }
        if ((tid & 31) == 0) s_wmax[tid >> 5] = key;
        __syncthreads();
        if (tid < 32) {
            ull k = (tid < 16) ? s_wmax[tid] : 0ull;
#pragma unroll
            for (int o = 8; o; o >>= 1) {
                ull k2 = __shfl_xor_sync(0xFFFFFFFFu, k, o);
                if (k2 > k) k = k2;
            }
            if (tid == 0) s_bkey = k;
        }
        __syncthreads();
        far = 0xFFFFFFFFu - (unsigned)(s_bkey & 0xFFFFFFFFull);
        cx = X[far]; cy = Y[far]; cz = Z[far];
    }
}

// ---------------- FPS stage 2: 512 -> 256 ----------------------------------
__global__ void __launch_bounds__(512, 1) k_fps2() {
    int b = blockIdx.x, tid = threadIdx.x;
    const float* P = g_nx1 + b * NP1 * 3;
    float px = P[tid * 3], py = P[tid * 3 + 1], pz = P[tid * 3 + 2];
    float dist = 1e10f;

    __shared__ ull s_wmax[16];
    __shared__ ull s_bkey;

    unsigned far = 0;
    float cx = P[0], cy = P[1], cz = P[2];

    for (int it = 0; it < NP2; ++it) {
        if (tid == 0) {
            g_fps2[b * NP2 + it] = (int)far;
            g_nx2[(b * NP2 + it) * 3 + 0] = cx;
            g_nx2[(b * NP2 + it) * 3 + 1] = cy;
            g_nx2[(b * NP2 + it) * 3 + 2] = cz;
        }
        float dx = px - cx, dy = py - cy, dz = pz - cz;
        dist = fminf(dist, dx * dx + dy * dy + dz * dz);

        ull key = ((ull)__float_as_uint(dist) << 32) | (ull)(0xFFFFFFFFu - (unsigned)tid);
#pragma unroll
        for (int o = 16; o; o >>= 1) {
            ull k2 = __shfl_xor_sync(0xFFFFFFFFu, key, o);
            if (k2 > key) key = k2;
        }
        if ((tid & 31) == 0) s_wmax[tid >> 5] = key;
        __syncthreads();
        if (tid < 32) {
            ull k = (tid < 16) ? s_wmax[tid] : 0ull;
#pragma unroll
            for (int o = 8; o; o >>= 1) {
                ull k2 = __shfl_xor_sync(0xFFFFFFFFu, k, o);
                if (k2 > k) k = k2;
            }
            if (tid == 0) s_bkey = k;
        }
        __syncthreads();
        far = 0xFFFFFFFFu - (unsigned)(s_bkey & 0xFFFFFFFFull);
        cx = P[far * 3]; cy = P[far * 3 + 1]; cz = P[far * 3 + 2];
    }
}

// ---------------- ball query 1: distinct in-ball indices, sorted -----------
__global__ void __launch_bounds__(256) k_bq1(const float* __restrict__ xyz) {
    int b  = blockIdx.x >> 6;
    int g0 = (blockIdx.x & 63) * 8;
    int t  = threadIdx.x;
    __shared__ float s_cx[8], s_cy[8], s_cz[8], s_cn[8];
    __shared__ int   s_cnt[8];
    __shared__ int   s_buf[8][CAP];

    if (t < 8) {
        int s  = g0 + t;
        int fi = g_fps1[b * NP1 + s];
        s_cx[t] = g_nx1[(b * NP1 + s) * 3 + 0];
        s_cy[t] = g_nx1[(b * NP1 + s) * 3 + 1];
        s_cz[t] = g_nx1[(b * NP1 + s) * 3 + 2];
        s_cn[t] = g_norms1[b * N1 + fi];
        s_cnt[t] = 0;
    }
    __syncthreads();

    const float* X  = xyz + (size_t)b * 6 * N1;
    const float* Y  = X + N1;
    const float* Z  = X + 2 * N1;
    const float* NN = g_norms1 + b * N1;
    const float r2  = (float)(0.025 * 0.025);

    for (int p = t; p < N1; p += 256) {
        float x = X[p], y = Y[p], z = Z[p], nn = NN[p];
#pragma unroll
        for (int g = 0; g < 8; ++g) {
            float dot = s_cx[g] * x + s_cy[g] * y + s_cz[g] * z;
            float sq  = (s_cn[g] + nn) - 2.0f * dot;   // mimic ref formula
            if (sq <= r2) {
                int pos = atomicAdd(&s_cnt[g], 1);
                if (pos < CAP) s_buf[g][pos] = p;
            }
        }
    }
    __syncthreads();

    if (t < 8) {
        int s = g0 + t;
        int m = min(s_cnt[t], CAP);
        int* bf = s_buf[t];
        for (int i = 1; i < m; ++i) {              // insertion sort (m tiny)
            int key = bf[i], j = i - 1;
            while (j >= 0 && bf[j] > key) { bf[j + 1] = bf[j]; --j; }
            bf[j + 1] = key;
        }
        int K = min(m, NS1);
        if (K == 0) { bf[0] = g_fps1[b * NP1 + s]; K = 1; }
        g_cnt1[b * NP1 + s] = K;
        for (int i = 0; i < K; ++i) g_list1[(b * NP1 + s) * 64 + i] = bf[i];
    }
}

// ---------------- ball query 2 ---------------------------------------------
__global__ void __launch_bounds__(128) k_bq2() {
    int b  = blockIdx.x >> 5;
    int g0 = (blockIdx.x & 31) * 8;
    int t  = threadIdx.x;
    __shared__ float s_cx[8], s_cy[8], s_cz[8], s_cn[8];
    __shared__ int   s_cnt[8];
    __shared__ int   s_buf[8][CAP];

    if (t < 8) {
        int s  = g0 + t;
        int fi = g_fps2[b * NP2 + s];
        s_cx[t] = g_nx2[(b * NP2 + s) * 3 + 0];
        s_cy[t] = g_nx2[(b * NP2 + s) * 3 + 1];
        s_cz[t] = g_nx2[(b * NP2 + s) * 3 + 2];
        s_cn[t] = g_norms2[b * N2 + fi];
        s_cnt[t] = 0;
    }
    __syncthreads();

    const float r2 = (float)(0.05 * 0.05);
    for (int p = t; p < N2; p += 128) {
        float x  = g_nx1[(b * N2 + p) * 3 + 0];
        float y  = g_nx1[(b * N2 + p) * 3 + 1];
        float z  = g_nx1[(b * N2 + p) * 3 + 2];
        float nn = g_norms2[b * N2 + p];
#pragma unroll
        for (int g = 0; g < 8; ++g) {
            float dot = s_cx[g] * x + s_cy[g] * y + s_cz[g] * z;
            float sq  = (s_cn[g] + nn) - 2.0f * dot;
            if (sq <= r2) {
                int pos = atomicAdd(&s_cnt[g], 1);
                if (pos < CAP) s_buf[g][pos] = p;
            }
        }
    }
    __syncthreads();

    if (t < 8) {
        int s = g0 + t;
        int m = min(s_cnt[t], CAP);
        int* bf = s_buf[t];
        for (int i = 1; i < m; ++i) {
            int key = bf[i], j = i - 1;
            while (j >= 0 && bf[j] > key) { bf[j + 1] = bf[j]; --j; }
            bf[j + 1] = key;
        }
        int K = min(m, NS2);
        if (K == 0) { bf[0] = g_fps2[b * NP2 + s]; K = 1; }
        g_cnt2[b * NP2 + s] = K;
        for (int i = 0; i < K; ++i) g_list2[(b * NP2 + s) * 64 + i] = bf[i];
    }
}

// ---------------- SA1 MLP (6->64->64->128) + max, distinct points only -----
__global__ void __launch_bounds__(128) k_mlp1(const float* __restrict__ xyz,
                                              const float* __restrict__ b1,
                                              const float* __restrict__ b2,
                                              const float* __restrict__ b3) {
    int bs = blockIdx.x;          // b*512 + s
    int b  = bs >> 9;
    int t  = threadIdx.x;
    __shared__ float s_f[6], s_h1[64], s_h2[64], s_c[3];
    if (t < 3) s_c[t] = g_nx1[bs * 3 + t];
    int K = g_cnt1[bs];
    float macc = -3.402823466e38f;
    __syncthreads();

    for (int k = 0; k < K; ++k) {
        int n = g_list1[bs * 64 + k];
        if (t < 6) {
            float v = xyz[((size_t)b * 6 + t) * N1 + n];
            if (t < 3) v -= s_c[t];
            s_f[t] = v;
        }
        __syncthreads();
        if (t < 64) {
            float a = b1[t];
#pragma unroll
            for (int c = 0; c < 6; ++c) a = fmaf(g_w1t[c * 64 + t], s_f[c], a);
            s_h1[t] = fmaxf(a, 0.0f);
        }
        __syncthreads();
        if (t < 64) {
            float a = b2[t];
#pragma unroll
            for (int c = 0; c < 64; ++c) a = fmaf(g_w2t[c * 64 + t], s_h1[c], a);
            s_h2[t] = fmaxf(a, 0.0f);
        }
        __syncthreads();
        {
            float a = b3[t];
#pragma unroll
            for (int c = 0; c < 64; ++c) a = fmaf(g_w3t[c * 128 + t], s_h2[c], a);
            macc = fmaxf(macc, fmaxf(a, 0.0f));
        }
        __syncthreads();
    }
    g_feat1[bs * 128 + t] = macc;
}

// ---------------- SA2 MLP (131->128->128->285) + max -----------------------
__global__ void __launch_bounds__(288) k_mlp2(const float* __restrict__ b1,
                                              const float* __restrict__ b2,
                                              const float* __restrict__ b3,
                                              float* __restrict__ out) {
    int bs = blockIdx.x;          // b*256 + s
    int b  = bs >> 8;
    int t  = threadIdx.x;
    __shared__ float s_f[131], s_h1[128], s_h2[128], s_c[3];
    if (t < 3) s_c[t] = g_nx2[bs * 3 + t];
    int K = g_cnt2[bs];
    float macc = -3.402823466e38f;
    __syncthreads();

    for (int k = 0; k < K; ++k) {
        int n = g_list2[bs * 64 + k];
        if (t < 131) {
            float v;
            if (t < 3) v = g_nx1[(b * N2 + n) * 3 + t] - s_c[t];
            else       v = g_feat1[(b * N2 + n) * 128 + (t - 3)];
            s_f[t] = v;
        }
        __syncthreads();
        if (t < 128) {
            float a = b1[t];
#pragma unroll
            for (int c = 0; c < 131; ++c) a = fmaf(g_w1t2[c * 128 + t], s_f[c], a);
            s_h1[t] = fmaxf(a, 0.0f);
        }
        __syncthreads();
        if (t < 128) {
            float a = b2[t];
#pragma unroll
            for (int c = 0; c < 128; ++c) a = fmaf(g_w2t2[c * 128 + t], s_h1[c], a);
            s_h2[t] = fmaxf(a, 0.0f);
        }
        __syncthreads();
        if (t < 285) {
            float a = b3[t];
#pragma unroll
            for (int c = 0; c < 128; ++c) a = fmaf(g_w3t2[c * 285 + t], s_h2[c], a);
            macc = fmaxf(macc, fmaxf(a, 0.0f));
        }
        __syncthreads();
    }
    if (t < 285) out[B * 3 * NP2 + bs * 285 + t] = macc;  // l2_points (B,256,285)
}

// ---------------- l2_xyz output: (B,3,256) ---------------------------------
__global__ void k_out_xyz(float* __restrict__ out) {
    int i = blockIdx.x * 256 + threadIdx.x;
    if (i < B * 3 * NP2) {
        int b = i / (3 * NP2);
        int r = i % (3 * NP2);
        int d = r / NP2;
        int s = r % NP2;
        out[i] = g_nx2[(b * NP2 + s) * 3 + d];
    }
}

// ---------------- launch ----------------------------------------------------
extern "C" void kernel_launch(void* const* d_in, const int* in_sizes, int n_in,
                              void* d_out, int out_size) {
    (void)in_sizes; (void)n_in; (void)out_size;
    const float* xyz = (const float*)d_in[0];
    const float* w1  = (const float*)d_in[1];  const float* bb1 = (const float*)d_in[2];
    const float* w2  = (const float*)d_in[3];  const float* bb2 = (const float*)d_in[4];
    const float* w3  = (const float*)d_in[5];  const float* bb3 = (const float*)d_in[6];
    const float* u1  = (const float*)d_in[7];  const float* cc1 = (const float*)d_in[8];
    const float* u2  = (const float*)d_in[9];  const float* cc2 = (const float*)d_in[10];
    const float* u3  = (const float*)d_in[11]; const float* cc3 = (const float*)d_in[12];
    float* out = (float*)d_out;

    k_transpose_all<<<(82304 + 255) / 256, 256>>>(w1, w2, w3, u1, u2, u3);
    k_norms1<<<(B * N1) / 256, 256>>>(xyz);
    k_fps1<<<B, 512>>>(xyz);
    k_bq1<<<B * 64, 256>>>(xyz);
    k_mlp1<<<B * NP1, 128>>>(xyz, bb1, bb2, bb3);
    k_norms2<<<(B * N2 + 255) / 256, 256>>>();
    k_fps2<<<B, 512>>>();
    k_bq2<<<B * 32, 128>>>();
    k_mlp2<<<B * NP2, 288>>>(cc1, cc2, cc3, out);
    k_out_xyz<<<(B * 3 * NP2 + 255) / 256, 256>>>(out);
}

// round 8
// speedup vs baseline: 5.3369x; 5.3369x over previous
#include <cuda_runtime.h>
#include <math.h>
#include <stdint.h>

#define B   8
#define N1  32768
#define NP1 512
#define NS1 32
#define N2  512
#define NP2 256
#define NS2 64
#define CAP 128

#define FCL 8          // cluster size for fps1
#define FPTS 4096      // points per CTA
#define FPPT 8         // points per thread (512 threads)

typedef unsigned long long ull;

// ---------------- scratch (device globals; no allocations) ----------------
__device__ float g_w1t [6  * 64 ];
__device__ float g_w2t [64 * 64 ];
__device__ float g_w3t [64 * 128];
__device__ float g_w1t2[131 * 128];
__device__ float g_w2t2[128 * 128];
__device__ float g_w3t2[128 * 285];

__device__ float g_norms1[B * N1];
__device__ int   g_fps1 [B * NP1];
__device__ float g_nx1  [B * NP1 * 3];
__device__ int   g_cnt1 [B * NP1];
__device__ int   g_list1[B * NP1 * 64];
__device__ float g_feat1[B * NP1 * 128];

__device__ float g_norms2[B * N2];
__device__ int   g_fps2 [B * NP2];
__device__ float g_nx2  [B * NP2 * 3];
__device__ int   g_cnt2 [B * NP2];
__device__ int   g_list2[B * NP2 * 64];

// ---------------- cluster helpers ------------------------------------------
__device__ __forceinline__ uint32_t s2u(const void* p) {
    return (uint32_t)__cvta_generic_to_shared(p);
}
__device__ __forceinline__ unsigned cl_rank() {
    unsigned r; asm("mov.u32 %0, %%cluster_ctarank;" : "=r"(r)); return r;
}
__device__ __forceinline__ void cluster_sync() {
    asm volatile("barrier.cluster.arrive.aligned;" ::: "memory");
    asm volatile("barrier.cluster.wait.aligned;" ::: "memory");
}
__device__ __forceinline__ void st_remote_u64(uint32_t laddr, unsigned rank, ull v) {
    asm volatile("{ .reg .b32 ra; mapa.shared::cluster.u32 ra, %0, %1; "
                 "st.shared::cluster.b64 [ra], %2; }"
                 :: "r"(laddr), "r"(rank), "l"(v) : "memory");
}
__device__ __forceinline__ void st_remote_u32(uint32_t laddr, unsigned rank, unsigned v) {
    asm volatile("{ .reg .b32 ra; mapa.shared::cluster.u32 ra, %0, %1; "
                 "st.shared::cluster.b32 [ra], %2; }"
                 :: "r"(laddr), "r"(rank), "r"(v) : "memory");
}
__device__ __forceinline__ void arrive_remote(uint32_t lbar, unsigned rank) {
    asm volatile("{ .reg .b32 ra; mapa.shared::cluster.u32 ra, %0, %1; "
                 "mbarrier.arrive.release.cluster.shared::cluster.b64 _, [ra]; }"
                 :: "r"(lbar), "r"(rank) : "memory");
}
__device__ __forceinline__ void mbar_wait_cluster(uint32_t mbar, unsigned parity) {
    asm volatile(
        "{\n\t"
        ".reg .pred P1;\n\t"
        "WAIT_LOOP_%=:\n\t"
        "mbarrier.try_wait.parity.acquire.cluster.shared::cta.b64 P1, [%0], %1, 0x989680;\n\t"
        "@P1 bra.uni WAIT_DONE_%=;\n\t"
        "bra.uni WAIT_LOOP_%=;\n\t"
        "WAIT_DONE_%=:\n\t"
        "}" :: "r"(mbar), "r"(parity) : "memory");
}

// ---------------- weight transpose: W[o][c] -> Wt[c][o] --------------------
__global__ void k_transpose_all(const float* __restrict__ w1, const float* __restrict__ w2,
                                const float* __restrict__ w3, const float* __restrict__ u1,
                                const float* __restrict__ u2, const float* __restrict__ u3) {
    int i = blockIdx.x * 256 + threadIdx.x;
    if (i < 384) {                              // 64x6
        int o = i / 6, c = i % 6;               g_w1t [c * 64  + o] = w1[i];
    } else if (i < 4480) {                      // 64x64
        int j = i - 384;  int o = j / 64,  c = j % 64;  g_w2t [c * 64  + o] = w2[j];
    } else if (i < 12672) {                     // 128x64
        int j = i - 4480; int o = j / 64,  c = j % 64;  g_w3t [c * 128 + o] = w3[j];
    } else if (i < 29440) {                     // 128x131
        int j = i - 12672;int o = j / 131, c = j % 131; g_w1t2[c * 128 + o] = u1[j];
    } else if (i < 45824) {                     // 128x128
        int j = i - 29440;int o = j / 128, c = j % 128; g_w2t2[c * 128 + o] = u2[j];
    } else if (i < 82304) {                     // 285x128
        int j = i - 45824;int o = j / 128, c = j % 128; g_w3t2[c * 285 + o] = u3[j];
    }
}

// ---------------- squared norms --------------------------------------------
__global__ void k_norms1(const float* __restrict__ xyz) {
    int i = blockIdx.x * 256 + threadIdx.x;
    if (i < B * N1) {
        int b = i >> 15, n = i & (N1 - 1);
        const float* base = xyz + (size_t)b * 6 * N1;
        float x = base[n], y = base[N1 + n], z = base[2 * N1 + n];
        g_norms1[i] = (x * x + y * y) + z * z;
    }
}

__global__ void k_norms2() {
    int i = blockIdx.x * 256 + threadIdx.x;
    if (i < B * N2) {
        float x = g_nx1[i * 3], y = g_nx1[i * 3 + 1], z = g_nx1[i * 3 + 2];
        g_norms2[i] = (x * x + y * y) + z * z;
    }
}

// ---------------- FPS stage 1: cluster of 8 CTAs per batch ------------------
// Each CTA owns 4096 points, all state in registers. Per iteration each CTA
// broadcasts its local-best (key, coords) into every peer's SMEM and arrives
// on every peer's mbarrier; a single parity wait is the only per-iter sync.
__global__ void __launch_bounds__(512, 1) __cluster_dims__(FCL, 1, 1)
k_fps1(const float* __restrict__ xyz) {
    int b = blockIdx.x / FCL;
    unsigned rank = cl_rank();
    int tid = threadIdx.x;
    const float* X = xyz + (size_t)b * 6 * N1;
    const float* Y = X + N1;
    const float* Z = X + 2 * N1;
    int base = rank * FPTS;

    float px[FPPT], py[FPPT], pz[FPPT], dist[FPPT];
#pragma unroll
    for (int j = 0; j < FPPT; ++j) {
        int p = base + j * 512 + tid;
        px[j] = X[p]; py[j] = Y[p]; pz[j] = Z[p];
        dist[j] = 1e10f;
    }

    __shared__ ull   s_wmax[16];
    __shared__ ull   s_key[2][FCL];
    __shared__ ull   s_cxy[2][FCL];
    __shared__ float s_cz [2][FCL];
    __shared__ ull   s_mbar;

    uint32_t bar = s2u(&s_mbar);
    if (tid == 0) {
        asm volatile("mbarrier.init.shared.b64 [%0], %1;" :: "r"(bar), "r"((unsigned)FCL) : "memory");
        asm volatile("fence.mbarrier_init.release.cluster;" ::: "memory");
    }
    __syncthreads();
    cluster_sync();

    unsigned far = 0;
    float cx = X[0], cy = Y[0], cz = Z[0];

    for (int it = 0; it < NP1; ++it) {
        unsigned par = (unsigned)(it & 1);
        if (rank == 0 && tid == 0) {
            g_fps1[b * NP1 + it] = (int)far;
            g_nx1[(b * NP1 + it) * 3 + 0] = cx;
            g_nx1[(b * NP1 + it) * 3 + 1] = cy;
            g_nx1[(b * NP1 + it) * 3 + 2] = cz;
        }
        // update + thread-local argmax
        float bv = -1.0f; unsigned bi = 0;
#pragma unroll
        for (int j = 0; j < FPPT; ++j) {
            float dx = px[j] - cx, dy = py[j] - cy, dz = pz[j] - cz;
            float d  = dx * dx + dy * dy + dz * dz;
            float nd = fminf(dist[j], d);
            dist[j] = nd;
            if (nd > bv) { bv = nd; bi = (unsigned)(base + j * 512 + tid); }
        }
        ull key = ((ull)__float_as_uint(bv) << 32) | (ull)(0xFFFFFFFFu - bi);
#pragma unroll
        for (int o = 16; o; o >>= 1) {
            ull k2 = __shfl_xor_sync(0xFFFFFFFFu, key, o);
            if (k2 > key) key = k2;
        }
        if ((tid & 31) == 0) s_wmax[tid >> 5] = key;
        __syncthreads();

        if (tid < 32) {
            ull k = (tid < 16) ? s_wmax[tid] : 0ull;
#pragma unroll
            for (int o = 8; o; o >>= 1) {
                ull k2 = __shfl_xor_sync(0xFFFFFFFFu, k, o);
                if (k2 > k) k = k2;
            }
            // lanes 0..7 each push CTA-best to peer rank == lane
            if (tid < FCL) {
                unsigned lidx = 0xFFFFFFFFu - (unsigned)(k & 0xFFFFFFFFull);
                float bx = X[lidx], by = Y[lidx], bz = Z[lidx];
                ull cxy;
                asm("mov.b64 %0, {%1, %2};" : "=l"(cxy) : "f"(bx), "f"(by));
                st_remote_u64(s2u(&s_key[par][rank]), (unsigned)tid, k);
                st_remote_u64(s2u(&s_cxy[par][rank]), (unsigned)tid, cxy);
                st_remote_u32(s2u(&s_cz [par][rank]), (unsigned)tid, __float_as_uint(bz));
                arrive_remote(bar, (unsigned)tid);
            }
        }

        mbar_wait_cluster(bar, par);

        // global best among the 8 slots
        ull best = s_key[par][0]; int bs = 0;
#pragma unroll
        for (int q = 1; q < FCL; ++q) {
            ull kq = s_key[par][q];
            if (kq > best) { best = kq; bs = q; }
        }
        far = 0xFFFFFFFFu - (unsigned)(best & 0xFFFFFFFFull);
        ull cxy = s_cxy[par][bs];
        float ncx, ncy;
        asm("mov.b64 {%0, %1}, %2;" : "=f"(ncx), "=f"(ncy) : "l"(cxy));
        cx = ncx; cy = ncy; cz = s_cz[par][bs];
    }
    cluster_sync();
}

// ---------------- FPS stage 2: 512 -> 256 ----------------------------------
__global__ void __launch_bounds__(512, 1) k_fps2() {
    int b = blockIdx.x, tid = threadIdx.x;
    const float* P = g_nx1 + b * NP1 * 3;
    float px = P[tid * 3], py = P[tid * 3 + 1], pz = P[tid * 3 + 2];
    float dist = 1e10f;

    __shared__ ull s_wmax[16];
    __shared__ ull s_bkey;

    unsigned far = 0;
    float cx = P[0], cy = P[1], cz = P[2];

    for (int it = 0; it < NP2; ++it) {
        if (tid == 0) {
            g_fps2[b * NP2 + it] = (int)far;
            g_nx2[(b * NP2 + it) * 3 + 0] = cx;
            g_nx2[(b * NP2 + it) * 3 + 1] = cy;
            g_nx2[(b * NP2 + it) * 3 + 2] = cz;
        }
        float dx = px - cx, dy = py - cy, dz = pz - cz;
        dist = fminf(dist, dx * dx + dy * dy + dz * dz);

        ull key = ((ull)__float_as_uint(dist) << 32) | (ull)(0xFFFFFFFFu - (unsigned)tid);
#pragma unroll
        for (int o = 16; o; o >>= 1) {
            ull k2 = __shfl_xor_sync(0xFFFFFFFFu, key, o);
            if (k2 > key) key = k2;
        }
        if ((tid & 31) == 0) s_wmax[tid >> 5] = key;
        __syncthreads();
        if (tid < 32) {
            ull k = (tid < 16) ? s_wmax[tid] : 0ull;
#pragma unroll
            for (int o = 8; o; o >>= 1) {
                ull k2 = __shfl_xor_sync(0xFFFFFFFFu, k, o);
                if (k2 > k) k = k2;
            }
            if (tid == 0) s_bkey = k;
        }
        __syncthreads();
        far = 0xFFFFFFFFu - (unsigned)(s_bkey & 0xFFFFFFFFull);
        cx = P[far * 3]; cy = P[far * 3 + 1]; cz = P[far * 3 + 2];
    }
}

// ---------------- ball query 1: 16 centroids/block, register-resident ------
__global__ void __launch_bounds__(256) k_bq1(const float* __restrict__ xyz) {
    int b  = blockIdx.x >> 5;             // 32 blocks per batch
    int g0 = (blockIdx.x & 31) * 16;
    int t  = threadIdx.x;
    __shared__ int s_cnt[16];
    __shared__ int s_buf[16][CAP];
    if (t < 16) s_cnt[t] = 0;

    float cxr[16], cyr[16], czr[16], cnr[16];
#pragma unroll
    for (int g = 0; g < 16; ++g) {
        int s  = g0 + g;
        int fi = g_fps1[b * NP1 + s];
        cxr[g] = g_nx1[(b * NP1 + s) * 3 + 0];
        cyr[g] = g_nx1[(b * NP1 + s) * 3 + 1];
        czr[g] = g_nx1[(b * NP1 + s) * 3 + 2];
        cnr[g] = g_norms1[b * N1 + fi];
    }
    __syncthreads();

    const float* X  = xyz + (size_t)b * 6 * N1;
    const float* Y  = X + N1;
    const float* Z  = X + 2 * N1;
    const float* NN = g_norms1 + b * N1;
    const float r2  = (float)(0.025 * 0.025);

    for (int p = t; p < N1; p += 256) {
        float x = X[p], y = Y[p], z = Z[p], nn = NN[p];
#pragma unroll
        for (int g = 0; g < 16; ++g) {
            float dot = cxr[g] * x + cyr[g] * y + czr[g] * z;
            float sq  = (cnr[g] + nn) - 2.0f * dot;   // mimic ref formula
            if (sq <= r2) {
                int pos = atomicAdd(&s_cnt[g], 1);
                if (pos < CAP) s_buf[g][pos] = p;
            }
        }
    }
    __syncthreads();

    if (t < 16) {
        int s = g0 + t;
        int m = min(s_cnt[t], CAP);
        int* bf = s_buf[t];
        for (int i = 1; i < m; ++i) {              // insertion sort (m tiny)
            int key = bf[i], j = i - 1;
            while (j >= 0 && bf[j] > key) { bf[j + 1] = bf[j]; --j; }
            bf[j + 1] = key;
        }
        int K = min(m, NS1);
        if (K == 0) { bf[0] = g_fps1[b * NP1 + s]; K = 1; }
        g_cnt1[b * NP1 + s] = K;
        for (int i = 0; i < K; ++i) g_list1[(b * NP1 + s) * 64 + i] = bf[i];
    }
}

// ---------------- ball query 2 ---------------------------------------------
__global__ void __launch_bounds__(128) k_bq2() {
    int b  = blockIdx.x >> 5;
    int g0 = (blockIdx.x & 31) * 8;
    int t  = threadIdx.x;
    __shared__ float s_cx[8], s_cy[8], s_cz[8], s_cn[8];
    __shared__ int   s_cnt[8];
    __shared__ int   s_buf[8][CAP];

    if (t < 8) {
        int s  = g0 + t;
        int fi = g_fps2[b * NP2 + s];
        s_cx[t] = g_nx2[(b * NP2 + s) * 3 + 0];
        s_cy[t] = g_nx2[(b * NP2 + s) * 3 + 1];
        s_cz[t] = g_nx2[(b * NP2 + s) * 3 + 2];
        s_cn[t] = g_norms2[b * N2 + fi];
        s_cnt[t] = 0;
    }
    __syncthreads();

    const float r2 = (float)(0.05 * 0.05);
    for (int p = t; p < N2; p += 128) {
        float x  = g_nx1[(b * N2 + p) * 3 + 0];
        float y  = g_nx1[(b * N2 + p) * 3 + 1];
        float z  = g_nx1[(b * N2 + p) * 3 + 2];
        float nn = g_norms2[b * N2 + p];
#pragma unroll
        for (int g = 0; g < 8; ++g) {
            float dot = s_cx[g] * x + s_cy[g] * y + s_cz[g] * z;
            float sq  = (s_cn[g] + nn) - 2.0f * dot;
            if (sq <= r2) {
                int pos = atomicAdd(&s_cnt[g], 1);
                if (pos < CAP) s_buf[g][pos] = p;
            }
        }
    }
    __syncthreads();

    if (t < 8) {
        int s = g0 + t;
        int m = min(s_cnt[t], CAP);
        int* bf = s_buf[t];
        for (int i = 1; i < m; ++i) {
            int key = bf[i], j = i - 1;
            while (j >= 0 && bf[j] > key) { bf[j + 1] = bf[j]; --j; }
            bf[j + 1] = key;
        }
        int K = min(m, NS2);
        if (K == 0) { bf[0] = g_fps2[b * NP2 + s]; K = 1; }
        g_cnt2[b * NP2 + s] = K;
        for (int i = 0; i < K; ++i) g_list2[(b * NP2 + s) * 64 + i] = bf[i];
    }
}

// ---------------- SA1 MLP (6->64->64->128) + max, distinct points only -----
__global__ void __launch_bounds__(128) k_mlp1(const float* __restrict__ xyz,
                                              const float* __restrict__ b1,
                                              const float* __restrict__ b2,
                                              const float* __restrict__ b3) {
    int bs = blockIdx.x;          // b*512 + s
    int b  = bs >> 9;
    int t  = threadIdx.x;
    __shared__ float s_f[6], s_h1[64], s_h2[64], s_c[3];
    if (t < 3) s_c[t] = g_nx1[bs * 3 + t];
    int K = g_cnt1[bs];
    float macc = -3.402823466e38f;
    __syncthreads();

    for (int k = 0; k < K; ++k) {
        int n = g_list1[bs * 64 + k];
        if (t < 6) {
            float v = xyz[((size_t)b * 6 + t) * N1 + n];
            if (t < 3) v -= s_c[t];
            s_f[t] = v;
        }
        __syncthreads();
        if (t < 64) {
            float a = b1[t];
#pragma unroll
            for (int c = 0; c < 6; ++c) a = fmaf(g_w1t[c * 64 + t], s_f[c], a);
            s_h1[t] = fmaxf(a, 0.0f);
        }
        __syncthreads();
        if (t < 64) {
            float a = b2[t];
#pragma unroll
            for (int c = 0; c < 64; ++c) a = fmaf(g_w2t[c * 64 + t], s_h1[c], a);
            s_h2[t] = fmaxf(a, 0.0f);
        }
        __syncthreads();
        {
            float a = b3[t];
#pragma unroll
            for (int c = 0; c < 64; ++c) a = fmaf(g_w3t[c * 128 + t], s_h2[c], a);
            macc = fmaxf(macc, fmaxf(a, 0.0f));
        }
        __syncthreads();
    }
    g_feat1[bs * 128 + t] = macc;
}

// ---------------- SA2 MLP (131->128->128->285) + max -----------------------
__global__ void __launch_bounds__(288) k_mlp2(const float* __restrict__ b1,
                                              const float* __restrict__ b2,
                                              const float* __restrict__ b3,
                                              float* __restrict__ out) {
    int bs = blockIdx.x;          // b*256 + s
    int b  = bs >> 8;
    int t  = threadIdx.x;
    __shared__ float s_f[131], s_h1[128], s_h2[128], s_c[3];
    if (t < 3) s_c[t] = g_nx2[bs * 3 + t];
    int K = g_cnt2[bs];
    float macc = -3.402823466e38f;
    __syncthreads();

    for (int k = 0; k < K; ++k) {
        int n = g_list2[bs * 64 + k];
        if (t < 131) {
            float v;
            if (t < 3) v = g_nx1[(b * N2 + n) * 3 + t] - s_c[t];
            else       v = g_feat1[(b * N2 + n) * 128 + (t - 3)];
            s_f[t] = v;
        }
        __syncthreads();
        if (t < 128) {
            float a = b1[t];
#pragma unroll
            for (int c = 0; c < 131; ++c) a = fmaf(g_w1t2[c * 128 + t], s_f[c], a);
            s_h1[t] = fmaxf(a, 0.0f);
        }
        __syncthreads();
        if (t < 128) {
            float a = b2[t];
#pragma unroll
            for (int c = 0; c < 128; ++c) a = fmaf(g_w2t2[c * 128 + t], s_h1[c], a);
            s_h2[t] = fmaxf(a, 0.0f);
        }
        __syncthreads();
        if (t < 285) {
            float a = b3[t];
#pragma unroll
            for (int c = 0; c < 128; ++c) a = fmaf(g_w3t2[c * 285 + t], s_h2[c], a);
            macc = fmaxf(macc, fmaxf(a, 0.0f));
        }
        __syncthreads();
    }
    if (t < 285) out[B * 3 * NP2 + bs * 285 + t] = macc;  // l2_points (B,256,285)
}

// ---------------- l2_xyz output: (B,3,256) ---------------------------------
__global__ void k_out_xyz(float* __restrict__ out) {
    int i = blockIdx.x * 256 + threadIdx.x;
    if (i < B * 3 * NP2) {
        int b = i / (3 * NP2);
        int r = i % (3 * NP2);
        int d = r / NP2;
        int s = r % NP2;
        out[i] = g_nx2[(b * NP2 + s) * 3 + d];
    }
}

// ---------------- launch ----------------------------------------------------
extern "C" void kernel_launch(void* const* d_in, const int* in_sizes, int n_in,
                              void* d_out, int out_size) {
    (void)in_sizes; (void)n_in; (void)out_size;
    const float* xyz = (const float*)d_in[0];
    const float* w1  = (const float*)d_in[1];  const float* bb1 = (const float*)d_in[2];
    const float* w2  = (const float*)d_in[3];  const float* bb2 = (const float*)d_in[4];
    const float* w3  = (const float*)d_in[5];  const float* bb3 = (const float*)d_in[6];
    const float* u1  = (const float*)d_in[7];  const float* cc1 = (const float*)d_in[8];
    const float* u2  = (const float*)d_in[9];  const float* cc2 = (const float*)d_in[10];
    const float* u3  = (const float*)d_in[11]; const float* cc3 = (const float*)d_in[12];
    float* out = (float*)d_out;

    k_transpose_all<<<(82304 + 255) / 256, 256>>>(w1, w2, w3, u1, u2, u3);
    k_norms1<<<(B * N1) / 256, 256>>>(xyz);
    k_fps1<<<B * FCL, 512>>>(xyz);
    k_bq1<<<B * 32, 256>>>(xyz);
    k_mlp1<<<B * NP1, 128>>>(xyz, bb1, bb2, bb3);
    k_norms2<<<(B * N2 + 255) / 256, 256>>>();
    k_fps2<<<B, 512>>>();
    k_bq2<<<B * 32, 128>>>();
    k_mlp2<<<B * NP2, 288>>>(cc1, cc2, cc3, out);
    k_out_xyz<<<(B * 3 * NP2 + 255) / 256, 256>>>(out);
}

// round 9
// speedup vs baseline: 5.5694x; 1.0436x over previous
#include <cuda_runtime.h>
#include <math.h>
#include <stdint.h>

#define B   8
#define N1  32768
#define NP1 512
#define NS1 32
#define N2  512
#define NP2 256
#define NS2 64
#define CAP 128
#define CCAP 96

#define FCL 8          // cluster size for fps1
#define FPTS 4096      // points per CTA
#define FPPT 8         // points per thread (512 threads)

#define G1  16         // centroids per bq1 block
#define SP1 8          // point splits per centroid group

typedef unsigned long long ull;

// ---------------- scratch (device globals; no allocations) ----------------
__device__ float g_w1t [6  * 64 ];
__device__ float g_w2t [64 * 64 ];
__device__ float g_w3t [64 * 128];
__device__ float g_w1t2[131 * 128];
__device__ float g_w2t2[128 * 128];
__device__ float g_w3t2[128 * 285];

__device__ float g_norms1[B * N1];
__device__ int   g_fps1 [B * NP1];
__device__ float g_nx1  [B * NP1 * 3];
__device__ int   g_cnt1 [B * NP1];
__device__ int   g_list1[B * NP1 * 64];
__device__ float g_feat1[B * NP1 * 128];
__device__ int   g_ccnt1[B * NP1];
__device__ int   g_coll1[B * NP1 * CCAP];

__device__ float g_norms2[B * N2];
__device__ int   g_fps2 [B * NP2];
__device__ float g_nx2  [B * NP2 * 3];
__device__ int   g_cnt2 [B * NP2];
__device__ int   g_list2[B * NP2 * 64];

// ---------------- cluster helpers ------------------------------------------
__device__ __forceinline__ uint32_t s2u(const void* p) {
    return (uint32_t)__cvta_generic_to_shared(p);
}
__device__ __forceinline__ unsigned cl_rank() {
    unsigned r; asm("mov.u32 %0, %%cluster_ctarank;" : "=r"(r)); return r;
}
__device__ __forceinline__ void cluster_sync() {
    asm volatile("barrier.cluster.arrive.aligned;" ::: "memory");
    asm volatile("barrier.cluster.wait.aligned;" ::: "memory");
}
__device__ __forceinline__ void st_remote_u64(uint32_t laddr, unsigned rank, ull v) {
    asm volatile("{ .reg .b32 ra; mapa.shared::cluster.u32 ra, %0, %1; "
                 "st.shared::cluster.b64 [ra], %2; }"
                 :: "r"(laddr), "r"(rank), "l"(v) : "memory");
}
__device__ __forceinline__ void st_remote_u32(uint32_t laddr, unsigned rank, unsigned v) {
    asm volatile("{ .reg .b32 ra; mapa.shared::cluster.u32 ra, %0, %1; "
                 "st.shared::cluster.b32 [ra], %2; }"
                 :: "r"(laddr), "r"(rank), "r"(v) : "memory");
}
__device__ __forceinline__ void arrive_remote(uint32_t lbar, unsigned rank) {
    asm volatile("{ .reg .b32 ra; mapa.shared::cluster.u32 ra, %0, %1; "
                 "mbarrier.arrive.release.cluster.shared::cluster.b64 _, [ra]; }"
                 :: "r"(lbar), "r"(rank) : "memory");
}
__device__ __forceinline__ void mbar_wait_cluster(uint32_t mbar, unsigned parity) {
    asm volatile(
        "{\n\t"
        ".reg .pred P1;\n\t"
        "WAIT_LOOP_%=:\n\t"
        "mbarrier.try_wait.parity.acquire.cluster.shared::cta.b64 P1, [%0], %1, 0x989680;\n\t"
        "@P1 bra.uni WAIT_DONE_%=;\n\t"
        "bra.uni WAIT_LOOP_%=;\n\t"
        "WAIT_DONE_%=:\n\t"
        "}" :: "r"(mbar), "r"(parity) : "memory");
}

// ---------------- init: zero collection counters ----------------------------
__global__ void k_init() {
    int i = blockIdx.x * 256 + threadIdx.x;
    if (i < B * NP1) g_ccnt1[i] = 0;
}

// ---------------- weight transpose: W[o][c] -> Wt[c][o] --------------------
__global__ void k_transpose_all(const float* __restrict__ w1, const float* __restrict__ w2,
                                const float* __restrict__ w3, const float* __restrict__ u1,
                                const float* __restrict__ u2, const float* __restrict__ u3) {
    int i = blockIdx.x * 256 + threadIdx.x;
    if (i < 384) {                              // 64x6
        int o = i / 6, c = i % 6;               g_w1t [c * 64  + o] = w1[i];
    } else if (i < 4480) {                      // 64x64
        int j = i - 384;  int o = j / 64,  c = j % 64;  g_w2t [c * 64  + o] = w2[j];
    } else if (i < 12672) {                     // 128x64
        int j = i - 4480; int o = j / 64,  c = j % 64;  g_w3t [c * 128 + o] = w3[j];
    } else if (i < 29440) {                     // 128x131
        int j = i - 12672;int o = j / 131, c = j % 131; g_w1t2[c * 128 + o] = u1[j];
    } else if (i < 45824) {                     // 128x128
        int j = i - 29440;int o = j / 128, c = j % 128; g_w2t2[c * 128 + o] = u2[j];
    } else if (i < 82304) {                     // 285x128
        int j = i - 45824;int o = j / 128, c = j % 128; g_w3t2[c * 285 + o] = u3[j];
    }
}

// ---------------- squared norms --------------------------------------------
__global__ void k_norms1(const float* __restrict__ xyz) {
    int i = blockIdx.x * 256 + threadIdx.x;
    if (i < B * N1) {
        int b = i >> 15, n = i & (N1 - 1);
        const float* base = xyz + (size_t)b * 6 * N1;
        float x = base[n], y = base[N1 + n], z = base[2 * N1 + n];
        g_norms1[i] = (x * x + y * y) + z * z;
    }
}

__global__ void k_norms2() {
    int i = blockIdx.x * 256 + threadIdx.x;
    if (i < B * N2) {
        float x = g_nx1[i * 3], y = g_nx1[i * 3 + 1], z = g_nx1[i * 3 + 2];
        g_norms2[i] = (x * x + y * y) + z * z;
    }
}

// ---------------- FPS stage 1: cluster of 8 CTAs per batch ------------------
// Winner coords are extracted from the winning thread's REGISTERS via warp
// shuffles (no L2 round-trip on the critical path).
__global__ void __launch_bounds__(512, 1) __cluster_dims__(FCL, 1, 1)
k_fps1(const float* __restrict__ xyz) {
    int b = blockIdx.x / FCL;
    unsigned rank = cl_rank();
    int tid = threadIdx.x;
    int lane = tid & 31, warp = tid >> 5;
    const float* X = xyz + (size_t)b * 6 * N1;
    const float* Y = X + N1;
    const float* Z = X + 2 * N1;
    unsigned base = rank * FPTS;

    float px[FPPT], py[FPPT], pz[FPPT], dist[FPPT];
#pragma unroll
    for (int j = 0; j < FPPT; ++j) {
        int p = base + j * 512 + tid;
        px[j] = X[p]; py[j] = Y[p]; pz[j] = Z[p];
        dist[j] = 1e10f;
    }

    __shared__ ull   s_wmax[16];
    __shared__ float s_wcx[16], s_wcy[16], s_wcz[16];
    __shared__ ull   s_key[2][FCL];
    __shared__ ull   s_cxy[2][FCL];
    __shared__ float s_cz [2][FCL];
    __shared__ ull   s_mbar;

    uint32_t bar = s2u(&s_mbar);
    if (tid == 0) {
        asm volatile("mbarrier.init.shared.b64 [%0], %1;" :: "r"(bar), "r"((unsigned)FCL) : "memory");
        asm volatile("fence.mbarrier_init.release.cluster;" ::: "memory");
    }
    __syncthreads();
    cluster_sync();

    unsigned far = 0;
    float cx = X[0], cy = Y[0], cz = Z[0];

    for (int it = 0; it < NP1; ++it) {
        unsigned par = (unsigned)(it & 1);
        if (rank == 0 && tid == 0) {
            g_fps1[b * NP1 + it] = (int)far;
            g_nx1[(b * NP1 + it) * 3 + 0] = cx;
            g_nx1[(b * NP1 + it) * 3 + 1] = cy;
            g_nx1[(b * NP1 + it) * 3 + 2] = cz;
        }
        // update + thread-local argmax
        float bv = -1.0f; unsigned bi = 0;
#pragma unroll
        for (int j = 0; j < FPPT; ++j) {
            float dx = px[j] - cx, dy = py[j] - cy, dz = pz[j] - cz;
            float d  = dx * dx + dy * dy + dz * dz;
            float nd = fminf(dist[j], d);
            dist[j] = nd;
            if (nd > bv) { bv = nd; bi = base + (unsigned)(j * 512 + tid); }
        }
        ull key = ((ull)__float_as_uint(bv) << 32) | (ull)(0xFFFFFFFFu - bi);
#pragma unroll
        for (int o = 16; o; o >>= 1) {
            ull k2 = __shfl_xor_sync(0xFFFFFFFFu, key, o);
            if (k2 > key) key = k2;
        }
        // extract winner coords from winner thread's registers (warp-local)
        {
            unsigned p  = 0xFFFFFFFFu - (unsigned)(key & 0xFFFFFFFFull);
            unsigned lc = p - base;
            unsigned jw = lc >> 9;
            unsigned wl = lc & 31;
            float sx = px[0], sy = py[0], sz = pz[0];
#pragma unroll
            for (int j = 1; j < FPPT; ++j) {
                if (jw == (unsigned)j) { sx = px[j]; sy = py[j]; sz = pz[j]; }
            }
            sx = __shfl_sync(0xFFFFFFFFu, sx, wl);
            sy = __shfl_sync(0xFFFFFFFFu, sy, wl);
            sz = __shfl_sync(0xFFFFFFFFu, sz, wl);
            if (lane == 0) {
                s_wmax[warp] = key;
                s_wcx[warp] = sx; s_wcy[warp] = sy; s_wcz[warp] = sz;
            }
        }
        __syncthreads();

        if (tid < 32) {
            ull ko = (tid < 16) ? s_wmax[tid] : 0ull;
            ull k = ko;
#pragma unroll
            for (int o = 8; o; o >>= 1) {
                ull k2 = __shfl_xor_sync(0xFFFFFFFFu, k, o);
                if (k2 > k) k = k2;
            }
            unsigned bal = __ballot_sync(0xFFFFFFFFu, (ko == k) && (tid < 16));
            int w = __ffs(bal) - 1;
            if (tid < FCL) {
                float bx = s_wcx[w], by = s_wcy[w], bz = s_wcz[w];
                ull cxy;
                asm("mov.b64 %0, {%1, %2};" : "=l"(cxy) : "f"(bx), "f"(by));
                st_remote_u64(s2u(&s_key[par][rank]), (unsigned)tid, k);
                st_remote_u64(s2u(&s_cxy[par][rank]), (unsigned)tid, cxy);
                st_remote_u32(s2u(&s_cz [par][rank]), (unsigned)tid, __float_as_uint(bz));
                arrive_remote(bar, (unsigned)tid);
            }
        }

        mbar_wait_cluster(bar, par);

        // global best among the 8 slots
        ull best = s_key[par][0]; int bs = 0;
#pragma unroll
        for (int q = 1; q < FCL; ++q) {
            ull kq = s_key[par][q];
            if (kq > best) { best = kq; bs = q; }
        }
        far = 0xFFFFFFFFu - (unsigned)(best & 0xFFFFFFFFull);
        ull cxy = s_cxy[par][bs];
        float ncx, ncy;
        asm("mov.b64 {%0, %1}, %2;" : "=f"(ncx), "=f"(ncy) : "l"(cxy));
        cx = ncx; cy = ncy; cz = s_cz[par][bs];
    }
    cluster_sync();
}

// ---------------- FPS stage 2: 512 -> 256 (SMEM-staged coords) --------------
__global__ void __launch_bounds__(512, 1) k_fps2() {
    int b = blockIdx.x, tid = threadIdx.x;
    __shared__ float s_px[512], s_py[512], s_pz[512];
    __shared__ ull s_wmax[16];
    __shared__ ull s_bkey;

    s_px[tid] = g_nx1[(b * NP1 + tid) * 3 + 0];
    s_py[tid] = g_nx1[(b * NP1 + tid) * 3 + 1];
    s_pz[tid] = g_nx1[(b * NP1 + tid) * 3 + 2];
    __syncthreads();

    float px = s_px[tid], py = s_py[tid], pz = s_pz[tid];
    float dist = 1e10f;
    unsigned far = 0;
    float cx = s_px[0], cy = s_py[0], cz = s_pz[0];

    for (int it = 0; it < NP2; ++it) {
        if (tid == 0) {
            g_fps2[b * NP2 + it] = (int)far;
            g_nx2[(b * NP2 + it) * 3 + 0] = cx;
            g_nx2[(b * NP2 + it) * 3 + 1] = cy;
            g_nx2[(b * NP2 + it) * 3 + 2] = cz;
        }
        float dx = px - cx, dy = py - cy, dz = pz - cz;
        dist = fminf(dist, dx * dx + dy * dy + dz * dz);

        ull key = ((ull)__float_as_uint(dist) << 32) | (ull)(0xFFFFFFFFu - (unsigned)tid);
#pragma unroll
        for (int o = 16; o; o >>= 1) {
            ull k2 = __shfl_xor_sync(0xFFFFFFFFu, key, o);
            if (k2 > key) key = k2;
        }
        if ((tid & 31) == 0) s_wmax[tid >> 5] = key;
        __syncthreads();
        if (tid < 32) {
            ull k = (tid < 16) ? s_wmax[tid] : 0ull;
#pragma unroll
            for (int o = 8; o; o >>= 1) {
                ull k2 = __shfl_xor_sync(0xFFFFFFFFu, k, o);
                if (k2 > k) k = k2;
            }
            if (tid == 0) s_bkey = k;
        }
        __syncthreads();
        far = 0xFFFFFFFFu - (unsigned)(s_bkey & 0xFFFFFFFFull);
        cx = s_px[far]; cy = s_py[far]; cz = s_pz[far];
    }
}

// ---------------- ball query 1: 16 centroids x 8 point-splits ---------------
__global__ void __launch_bounds__(256) k_bq1c(const float* __restrict__ xyz) {
    int bid   = blockIdx.x;
    int b     = bid / (32 * SP1);
    int rem   = bid % (32 * SP1);
    int grp   = rem / SP1;
    int split = rem % SP1;
    int g0    = grp * G1;
    int t     = threadIdx.x;

    __shared__ float s_cx[G1], s_cy[G1], s_cz[G1], s_cn[G1];
    if (t < G1) {
        int s  = g0 + t;
        int fi = g_fps1[b * NP1 + s];
        s_cx[t] = g_nx1[(b * NP1 + s) * 3 + 0];
        s_cy[t] = g_nx1[(b * NP1 + s) * 3 + 1];
        s_cz[t] = g_nx1[(b * NP1 + s) * 3 + 2];
        s_cn[t] = g_norms1[b * N1 + fi];
    }
    __syncthreads();

    float cxr[G1], cyr[G1], czr[G1], cnr[G1];
#pragma unroll
    for (int g = 0; g < G1; ++g) {
        cxr[g] = s_cx[g]; cyr[g] = s_cy[g]; czr[g] = s_cz[g]; cnr[g] = s_cn[g];
    }

    const float* X  = xyz + (size_t)b * 6 * N1;
    const float* Y  = X + N1;
    const float* Z  = X + 2 * N1;
    const float* NN = g_norms1 + b * N1;
    const float r2  = (float)(0.025 * 0.025);
    int p0 = split * (N1 / SP1);

#pragma unroll 1
    for (int i = 0; i < (N1 / SP1) / 256; ++i) {
        int p = p0 + i * 256 + t;
        float x = X[p], y = Y[p], z = Z[p], nn = NN[p];
#pragma unroll
        for (int g = 0; g < G1; ++g) {
            float dot = cxr[g] * x + cyr[g] * y + czr[g] * z;
            float sq  = (cnr[g] + nn) - 2.0f * dot;   // mimic ref formula
            if (sq <= r2) {
                int cent = b * NP1 + g0 + g;
                int pos = atomicAdd(&g_ccnt1[cent], 1);
                if (pos < CCAP) g_coll1[cent * CCAP + pos] = p;
            }
        }
    }
}

// sort + truncate per centroid
__global__ void k_bqfix1() {
    int idx = blockIdx.x * 256 + threadIdx.x;
    if (idx >= B * NP1) return;
    int m = min(g_ccnt1[idx], CCAP);
    int buf[CCAP];
    for (int i = 0; i < m; ++i) buf[i] = g_coll1[idx * CCAP + i];
    for (int i = 1; i < m; ++i) {
        int key = buf[i], j = i - 1;
        while (j >= 0 && buf[j] > key) { buf[j + 1] = buf[j]; --j; }
        buf[j + 1] = key;
    }
    int K = min(m, NS1);
    if (K == 0) { buf[0] = g_fps1[idx]; K = 1; }
    g_cnt1[idx] = K;
    for (int i = 0; i < K; ++i) g_list1[idx * 64 + i] = buf[i];
}

// ---------------- ball query 2 ---------------------------------------------
__global__ void __launch_bounds__(128) k_bq2() {
    int b  = blockIdx.x >> 5;
    int g0 = (blockIdx.x & 31) * 8;
    int t  = threadIdx.x;
    __shared__ float s_cx[8], s_cy[8], s_cz[8], s_cn[8];
    __shared__ int   s_cnt[8];
    __shared__ int   s_buf[8][CAP];

    if (t < 8) {
        int s  = g0 + t;
        int fi = g_fps2[b * NP2 + s];
        s_cx[t] = g_nx2[(b * NP2 + s) * 3 + 0];
        s_cy[t] = g_nx2[(b * NP2 + s) * 3 + 1];
        s_cz[t] = g_nx2[(b * NP2 + s) * 3 + 2];
        s_cn[t] = g_norms2[b * N2 + fi];
        s_cnt[t] = 0;
    }
    __syncthreads();

    const float r2 = (float)(0.05 * 0.05);
    for (int p = t; p < N2; p += 128) {
        float x  = g_nx1[(b * N2 + p) * 3 + 0];
        float y  = g_nx1[(b * N2 + p) * 3 + 1];
        float z  = g_nx1[(b * N2 + p) * 3 + 2];
        float nn = g_norms2[b * N2 + p];
#pragma unroll
        for (int g = 0; g < 8; ++g) {
            float dot = s_cx[g] * x + s_cy[g] * y + s_cz[g] * z;
            float sq  = (s_cn[g] + nn) - 2.0f * dot;
            if (sq <= r2) {
                int pos = atomicAdd(&s_cnt[g], 1);
                if (pos < CAP) s_buf[g][pos] = p;
            }
        }
    }
    __syncthreads();

    if (t < 8) {
        int s = g0 + t;
        int m = min(s_cnt[t], CAP);
        int* bf = s_buf[t];
        for (int i = 1; i < m; ++i) {
            int key = bf[i], j = i - 1;
            while (j >= 0 && bf[j] > key) { bf[j + 1] = bf[j]; --j; }
            bf[j + 1] = key;
        }
        int K = min(m, NS2);
        if (K == 0) { bf[0] = g_fps2[b * NP2 + s]; K = 1; }
        g_cnt2[b * NP2 + s] = K;
        for (int i = 0; i < K; ++i) g_list2[(b * NP2 + s) * 64 + i] = bf[i];
    }
}

// ---------------- SA1 MLP (6->64->64->128) + max, distinct points only -----
__global__ void __launch_bounds__(128) k_mlp1(const float* __restrict__ xyz,
                                              const float* __restrict__ b1,
                                              const float* __restrict__ b2,
                                              const float* __restrict__ b3) {
    int bs = blockIdx.x;          // b*512 + s
    int b  = bs >> 9;
    int t  = threadIdx.x;
    __shared__ float s_f[6], s_h1[64], s_h2[64], s_c[3];
    if (t < 3) s_c[t] = g_nx1[bs * 3 + t];
    int K = g_cnt1[bs];
    float macc = -3.402823466e38f;
    __syncthreads();

    for (int k = 0; k < K; ++k) {
        int n = g_list1[bs * 64 + k];
        if (t < 6) {
            float v = xyz[((size_t)b * 6 + t) * N1 + n];
            if (t < 3) v -= s_c[t];
            s_f[t] = v;
        }
        __syncthreads();
        if (t < 64) {
            float a = b1[t];
#pragma unroll
            for (int c = 0; c < 6; ++c) a = fmaf(g_w1t[c * 64 + t], s_f[c], a);
            s_h1[t] = fmaxf(a, 0.0f);
        }
        __syncthreads();
        if (t < 64) {
            float a = b2[t];
#pragma unroll
            for (int c = 0; c < 64; ++c) a = fmaf(g_w2t[c * 64 + t], s_h1[c], a);
            s_h2[t] = fmaxf(a, 0.0f);
        }
        __syncthreads();
        {
            float a = b3[t];
#pragma unroll
            for (int c = 0; c < 64; ++c) a = fmaf(g_w3t[c * 128 + t], s_h2[c], a);
            macc = fmaxf(macc, fmaxf(a, 0.0f));
        }
        __syncthreads();
    }
    g_feat1[bs * 128 + t] = macc;
}

// ---------------- SA2 MLP (131->128->128->285) + max -----------------------
__global__ void __launch_bounds__(288) k_mlp2(const float* __restrict__ b1,
                                              const float* __restrict__ b2,
                                              const float* __restrict__ b3,
                                              float* __restrict__ out) {
    int bs = blockIdx.x;          // b*256 + s
    int b  = bs >> 8;
    int t  = threadIdx.x;
    __shared__ float s_f[131], s_h1[128], s_h2[128], s_c[3];
    if (t < 3) s_c[t] = g_nx2[bs * 3 + t];
    int K = g_cnt2[bs];
    float macc = -3.402823466e38f;
    __syncthreads();

    for (int k = 0; k < K; ++k) {
        int n = g_list2[bs * 64 + k];
        if (t < 131) {
            float v;
            if (t < 3) v = g_nx1[(b * N2 + n) * 3 + t] - s_c[t];
            else       v = g_feat1[(b * N2 + n) * 128 + (t - 3)];
            s_f[t] = v;
        }
        __syncthreads();
        if (t < 128) {
            float a = b1[t];
#pragma unroll
            for (int c = 0; c < 131; ++c) a = fmaf(g_w1t2[c * 128 + t], s_f[c], a);
            s_h1[t] = fmaxf(a, 0.0f);
        }
        __syncthreads();
        if (t < 128) {
            float a = b2[t];
#pragma unroll
            for (int c = 0; c < 128; ++c) a = fmaf(g_w2t2[c * 128 + t], s_h1[c], a);
            s_h2[t] = fmaxf(a, 0.0f);
        }
        __syncthreads();
        if (t < 285) {
            float a = b3[t];
#pragma unroll
            for (int c = 0; c < 128; ++c) a = fmaf(g_w3t2[c * 285 + t], s_h2[c], a);
            macc = fmaxf(macc, fmaxf(a, 0.0f));
        }
        __syncthreads();
    }
    if (t < 285) out[B * 3 * NP2 + bs * 285 + t] = macc;  // l2_points (B,256,285)
}

// ---------------- l2_xyz output: (B,3,256) ---------------------------------
__global__ void k_out_xyz(float* __restrict__ out) {
    int i = blockIdx.x * 256 + threadIdx.x;
    if (i < B * 3 * NP2) {
        int b = i / (3 * NP2);
        int r = i % (3 * NP2);
        int d = r / NP2;
        int s = r % NP2;
        out[i] = g_nx2[(b * NP2 + s) * 3 + d];
    }
}

// ---------------- launch ----------------------------------------------------
extern "C" void kernel_launch(void* const* d_in, const int* in_sizes, int n_in,
                              void* d_out, int out_size) {
    (void)in_sizes; (void)n_in; (void)out_size;
    const float* xyz = (const float*)d_in[0];
    const float* w1  = (const float*)d_in[1];  const float* bb1 = (const float*)d_in[2];
    const float* w2  = (const float*)d_in[3];  const float* bb2 = (const float*)d_in[4];
    const float* w3  = (const float*)d_in[5];  const float* bb3 = (const float*)d_in[6];
    const float* u1  = (const float*)d_in[7];  const float* cc1 = (const float*)d_in[8];
    const float* u2  = (const float*)d_in[9];  const float* cc2 = (const float*)d_in[10];
    const float* u3  = (const float*)d_in[11]; const float* cc3 = (const float*)d_in[12];
    float* out = (float*)d_out;

    k_init<<<(B * NP1 + 255) / 256, 256>>>();
    k_transpose_all<<<(82304 + 255) / 256, 256>>>(w1, w2, w3, u1, u2, u3);
    k_norms1<<<(B * N1) / 256, 256>>>(xyz);
    k_fps1<<<B * FCL, 512>>>(xyz);
    k_bq1c<<<B * 32 * SP1, 256>>>(xyz);
    k_bqfix1<<<(B * NP1 + 255) / 256, 256>>>();
    k_mlp1<<<B * NP1, 128>>>(xyz, bb1, bb2, bb3);
    k_norms2<<<(B * N2 + 255) / 256, 256>>>();
    k_fps2<<<B, 512>>>();
    k_bq2<<<B * 32, 128>>>();
    k_mlp2<<<B * NP2, 288>>>(cc1, cc2, cc3, out);
    k_out_xyz<<<(B * 3 * NP2 + 255) / 256, 256>>>(out);
}

// round 10
// speedup vs baseline: 6.2534x; 1.1228x over previous
#include <cuda_runtime.h>
#include <math.h>
#include <stdint.h>

#define B   8
#define N1  32768
#define NP1 512
#define NS1 32
#define N2  512
#define NP2 256
#define NS2 64
#define CAP 128
#define CCAP 96

#define FCL 8          // cluster size for fps1
#define FPTS 4096      // points per CTA
#define FPPT 8         // points per thread (512 threads)

#define G1  16         // centroids per bq1 block
#define SP1 8          // point splits per centroid group

typedef unsigned long long ull;

// ---------------- scratch (device globals; no allocations) ----------------
__device__ float g_w1t [6  * 64 ];
__device__ float g_w2t [64 * 64 ];
__device__ float g_w3t [64 * 128];
__device__ float g_w1t2[131 * 128];
__device__ float g_w2t2[128 * 128];
__device__ float g_w3t2[128 * 285];

__device__ float g_norms1[B * N1];
__device__ int   g_fps1 [B * NP1];
__device__ float g_nx1  [B * NP1 * 3];
__device__ int   g_cnt1 [B * NP1];
__device__ int   g_list1[B * NP1 * 64];
__device__ float g_feat1[B * NP1 * 128];
__device__ int   g_ccnt1[B * NP1];
__device__ int   g_coll1[B * NP1 * CCAP];

__device__ float g_norms2[B * N2];
__device__ int   g_fps2 [B * NP2];
__device__ float g_nx2  [B * NP2 * 3];
__device__ int   g_cnt2 [B * NP2];
__device__ int   g_list2[B * NP2 * 64];

// ---------------- cluster helpers ------------------------------------------
__device__ __forceinline__ uint32_t s2u(const void* p) {
    return (uint32_t)__cvta_generic_to_shared(p);
}
__device__ __forceinline__ unsigned cl_rank() {
    unsigned r; asm("mov.u32 %0, %%cluster_ctarank;" : "=r"(r)); return r;
}
__device__ __forceinline__ void cluster_sync() {
    asm volatile("barrier.cluster.arrive.aligned;" ::: "memory");
    asm volatile("barrier.cluster.wait.aligned;" ::: "memory");
}
__device__ __forceinline__ void st_remote_u64(uint32_t laddr, unsigned rank, ull v) {
    asm volatile("{ .reg .b32 ra; mapa.shared::cluster.u32 ra, %0, %1; "
                 "st.shared::cluster.b64 [ra], %2; }"
                 :: "r"(laddr), "r"(rank), "l"(v) : "memory");
}
__device__ __forceinline__ void st_remote_u32(uint32_t laddr, unsigned rank, unsigned v) {
    asm volatile("{ .reg .b32 ra; mapa.shared::cluster.u32 ra, %0, %1; "
                 "st.shared::cluster.b32 [ra], %2; }"
                 :: "r"(laddr), "r"(rank), "r"(v) : "memory");
}
__device__ __forceinline__ void arrive_remote(uint32_t lbar, unsigned rank) {
    asm volatile("{ .reg .b32 ra; mapa.shared::cluster.u32 ra, %0, %1; "
                 "mbarrier.arrive.release.cluster.shared::cluster.b64 _, [ra]; }"
                 :: "r"(lbar), "r"(rank) : "memory");
}
__device__ __forceinline__ void mbar_wait_cluster(uint32_t mbar, unsigned parity) {
    asm volatile(
        "{\n\t"
        ".reg .pred P1;\n\t"
        "WAIT_LOOP_%=:\n\t"
        "mbarrier.try_wait.parity.acquire.cluster.shared::cta.b64 P1, [%0], %1, 0x989680;\n\t"
        "@P1 bra.uni WAIT_DONE_%=;\n\t"
        "bra.uni WAIT_LOOP_%=;\n\t"
        "WAIT_DONE_%=:\n\t"
        "}" :: "r"(mbar), "r"(parity) : "memory");
}

// ---------------- weight transpose + counter init ---------------------------
__global__ void k_transpose_all(const float* __restrict__ w1, const float* __restrict__ w2,
                                const float* __restrict__ w3, const float* __restrict__ u1,
                                const float* __restrict__ u2, const float* __restrict__ u3) {
    int i = blockIdx.x * 256 + threadIdx.x;
    if (i < 384) {                              // 64x6
        int o = i / 6, c = i % 6;               g_w1t [c * 64  + o] = w1[i];
    } else if (i < 4480) {                      // 64x64
        int j = i - 384;  int o = j / 64,  c = j % 64;  g_w2t [c * 64  + o] = w2[j];
    } else if (i < 12672) {                     // 128x64
        int j = i - 4480; int o = j / 64,  c = j % 64;  g_w3t [c * 128 + o] = w3[j];
    } else if (i < 29440) {                     // 128x131
        int j = i - 12672;int o = j / 131, c = j % 131; g_w1t2[c * 128 + o] = u1[j];
    } else if (i < 45824) {                     // 128x128
        int j = i - 29440;int o = j / 128, c = j % 128; g_w2t2[c * 128 + o] = u2[j];
    } else if (i < 82304) {                     // 285x128
        int j = i - 45824;int o = j / 128, c = j % 128; g_w3t2[c * 285 + o] = u3[j];
    } else if (i < 82304 + B * NP1) {           // zero bq1 collection counters
        g_ccnt1[i - 82304] = 0;
    }
}

// ---------------- squared norms --------------------------------------------
__global__ void k_norms1(const float* __restrict__ xyz) {
    int i = blockIdx.x * 256 + threadIdx.x;
    if (i < B * N1) {
        int b = i >> 15, n = i & (N1 - 1);
        const float* base = xyz + (size_t)b * 6 * N1;
        float x = base[n], y = base[N1 + n], z = base[2 * N1 + n];
        g_norms1[i] = (x * x + y * y) + z * z;
    }
}

__global__ void k_norms2() {
    int i = blockIdx.x * 256 + threadIdx.x;
    if (i < B * N2) {
        float x = g_nx1[i * 3], y = g_nx1[i * 3 + 1], z = g_nx1[i * 3 + 2];
        g_norms2[i] = (x * x + y * y) + z * z;
    }
}

// ---------------- FPS stage 1: cluster of 8 CTAs per batch ------------------
// REDUX-based reductions; all winner indices decoded arithmetically.
__global__ void __launch_bounds__(512, 1) __cluster_dims__(FCL, 1, 1)
k_fps1(const float* __restrict__ xyz) {
    int b = blockIdx.x / FCL;
    unsigned rank = cl_rank();
    int tid = threadIdx.x;
    int lane = tid & 31, warp = tid >> 5;
    const float* X = xyz + (size_t)b * 6 * N1;
    const float* Y = X + N1;
    const float* Z = X + 2 * N1;
    unsigned base = rank * FPTS;

    float px[FPPT], py[FPPT], pz[FPPT], dist[FPPT];
#pragma unroll
    for (int j = 0; j < FPPT; ++j) {
        int p = base + j * 512 + tid;
        px[j] = X[p]; py[j] = Y[p]; pz[j] = Z[p];
        dist[j] = 1e10f;
    }

    __shared__ unsigned s_wv[16], s_wbi[16];
    __shared__ float s_wcx[16], s_wcy[16], s_wcz[16];
    __shared__ ull   s_key[2][FCL];
    __shared__ ull   s_cxy[2][FCL];
    __shared__ float s_cz [2][FCL];
    __shared__ ull   s_mbar;

    uint32_t bar = s2u(&s_mbar);
    if (tid == 0) {
        asm volatile("mbarrier.init.shared.b64 [%0], %1;" :: "r"(bar), "r"((unsigned)FCL) : "memory");
        asm volatile("fence.mbarrier_init.release.cluster;" ::: "memory");
    }
    __syncthreads();
    cluster_sync();

    unsigned far = 0;
    float cx = X[0], cy = Y[0], cz = Z[0];

    for (int it = 0; it < NP1; ++it) {
        unsigned par = (unsigned)(it & 1);
        if (rank == 0 && tid == 0) {
            g_fps1[b * NP1 + it] = (int)far;
            g_nx1[(b * NP1 + it) * 3 + 0] = cx;
            g_nx1[(b * NP1 + it) * 3 + 1] = cy;
            g_nx1[(b * NP1 + it) * 3 + 2] = cz;
        }
        // update dists (parallel) + thread-local argmax via packed-key tree
        ull kk[FPPT];
#pragma unroll
        for (int j = 0; j < FPPT; ++j) {
            float dx = px[j] - cx, dy = py[j] - cy, dz = pz[j] - cz;
            float d  = dx * dx + dy * dy + dz * dz;
            float nd = fminf(dist[j], d);
            dist[j] = nd;
            unsigned bij = base + (unsigned)(j * 512 + tid);
            kk[j] = ((ull)__float_as_uint(nd) << 32) | (ull)(0xFFFFFFFFu - bij);
        }
#pragma unroll
        for (int s = FPPT / 2; s; s >>= 1)
#pragma unroll
            for (int i = 0; i < s; ++i)
                if (kk[i + s] > kk[i]) kk[i] = kk[i + s];
        unsigned vb = (unsigned)(kk[0] >> 32);
        unsigned bi = 0xFFFFFFFFu - (unsigned)(kk[0] & 0xFFFFFFFFull);

        // warp reduce via REDUX (max value, then min index among max holders)
        unsigned wmax = __reduce_max_sync(0xFFFFFFFFu, vb);
        unsigned cand = (vb == wmax) ? bi : 0xFFFFFFFFu;
        unsigned wbi  = __reduce_min_sync(0xFFFFFFFFu, cand);

        // winner coords from winner thread's registers (lane/j decoded from wbi)
        {
            unsigned lw = wbi & 31u;
            unsigned jw = (wbi & 4095u) >> 9;
            float sx = px[0], sy = py[0], sz = pz[0];
#pragma unroll
            for (int j = 1; j < FPPT; ++j) {
                if (jw == (unsigned)j) { sx = px[j]; sy = py[j]; sz = pz[j]; }
            }
            sx = __shfl_sync(0xFFFFFFFFu, sx, lw);
            sy = __shfl_sync(0xFFFFFFFFu, sy, lw);
            sz = __shfl_sync(0xFFFFFFFFu, sz, lw);
            if (lane == 0) {
                s_wv[warp] = wmax; s_wbi[warp] = wbi;
                s_wcx[warp] = sx;  s_wcy[warp] = sy; s_wcz[warp] = sz;
            }
        }
        __syncthreads();

        if (tid < 32) {
            unsigned v  = (tid < 16) ? s_wv[tid]  : 0u;
            unsigned bw = (tid < 16) ? s_wbi[tid] : 0xFFFFFFFFu;
            unsigned vmax = __reduce_max_sync(0xFFFFFFFFu, v);
            unsigned c2   = (v == vmax && tid < 16) ? bw : 0xFFFFFFFFu;
            unsigned bbi  = __reduce_min_sync(0xFFFFFFFFu, c2);
            if (tid < FCL) {
                unsigned w = (bbi & 511u) >> 5;        // winning warp in this CTA
                float bx = s_wcx[w], by = s_wcy[w], bz = s_wcz[w];
                ull key = ((ull)vmax << 32) | (ull)(0xFFFFFFFFu - bbi);
                ull cxy;
                asm("mov.b64 %0, {%1, %2};" : "=l"(cxy) : "f"(bx), "f"(by));
                st_remote_u64(s2u(&s_key[par][rank]), (unsigned)tid, key);
                st_remote_u64(s2u(&s_cxy[par][rank]), (unsigned)tid, cxy);
                st_remote_u32(s2u(&s_cz [par][rank]), (unsigned)tid, __float_as_uint(bz));
                arrive_remote(bar, (unsigned)tid);
            }
        }

        mbar_wait_cluster(bar, par);

        // global best among the 8 slots: depth-3 tree; slot decoded from index
        ull k0 = s_key[par][0], k1 = s_key[par][1], k2 = s_key[par][2], k3 = s_key[par][3];
        ull k4 = s_key[par][4], k5 = s_key[par][5], k6 = s_key[par][6], k7 = s_key[par][7];
        ull m0 = (k1 > k0) ? k1 : k0;
        ull m1 = (k3 > k2) ? k3 : k2;
        ull m2 = (k5 > k4) ? k5 : k4;
        ull m3 = (k7 > k6) ? k7 : k6;
        ull n0 = (m1 > m0) ? m1 : m0;
        ull n1 = (m3 > m2) ? m3 : m2;
        ull best = (n1 > n0) ? n1 : n0;
        far = 0xFFFFFFFFu - (unsigned)(best & 0xFFFFFFFFull);
        unsigned bs = far >> 12;                   // 4096 points per CTA
        ull cxy = s_cxy[par][bs];
        float ncx, ncy;
        asm("mov.b64 {%0, %1}, %2;" : "=f"(ncx), "=f"(ncy) : "l"(cxy));
        cx = ncx; cy = ncy; cz = s_cz[par][bs];
    }
    cluster_sync();
}

// ---------------- FPS stage 2: one warp per batch, all-register -------------
__global__ void __launch_bounds__(32, 1) k_fps2() {
    int b = blockIdx.x;
    int lane = threadIdx.x;

    float px[16], py[16], pz[16], dist[16];
#pragma unroll
    for (int j = 0; j < 16; ++j) {
        int p = j * 32 + lane;
        px[j] = g_nx1[(b * NP1 + p) * 3 + 0];
        py[j] = g_nx1[(b * NP1 + p) * 3 + 1];
        pz[j] = g_nx1[(b * NP1 + p) * 3 + 2];
        dist[j] = 1e10f;
    }

    unsigned far = 0;
    float cx = __shfl_sync(0xFFFFFFFFu, px[0], 0);
    float cy = __shfl_sync(0xFFFFFFFFu, py[0], 0);
    float cz = __shfl_sync(0xFFFFFFFFu, pz[0], 0);

    for (int it = 0; it < NP2; ++it) {
        if (lane == 0) {
            g_fps2[b * NP2 + it] = (int)far;
            g_nx2[(b * NP2 + it) * 3 + 0] = cx;
            g_nx2[(b * NP2 + it) * 3 + 1] = cy;
            g_nx2[(b * NP2 + it) * 3 + 2] = cz;
        }
        ull kk[16];
#pragma unroll
        for (int j = 0; j < 16; ++j) {
            float dx = px[j] - cx, dy = py[j] - cy, dz = pz[j] - cz;
            float d  = dx * dx + dy * dy + dz * dz;
            float nd = fminf(dist[j], d);
            dist[j] = nd;
            unsigned bij = (unsigned)(j * 32 + lane);
            kk[j] = ((ull)__float_as_uint(nd) << 32) | (ull)(0xFFFFFFFFu - bij);
        }
#pragma unroll
        for (int s = 8; s; s >>= 1)
#pragma unroll
            for (int i = 0; i < s; ++i)
                if (kk[i + s] > kk[i]) kk[i] = kk[i + s];
        unsigned vb = (unsigned)(kk[0] >> 32);
        unsigned bi = 0xFFFFFFFFu - (unsigned)(kk[0] & 0xFFFFFFFFull);

        unsigned wmax = __reduce_max_sync(0xFFFFFFFFu, vb);
        unsigned cand = (vb == wmax) ? bi : 0xFFFFFFFFu;
        unsigned wbi  = __reduce_min_sync(0xFFFFFFFFu, cand);

        unsigned lw = wbi & 31u;
        unsigned jw = wbi >> 5;
        float sx = px[0], sy = py[0], sz = pz[0];
#pragma unroll
        for (int j = 1; j < 16; ++j) {
            if (jw == (unsigned)j) { sx = px[j]; sy = py[j]; sz = pz[j]; }
        }
        cx = __shfl_sync(0xFFFFFFFFu, sx, lw);
        cy = __shfl_sync(0xFFFFFFFFu, sy, lw);
        cz = __shfl_sync(0xFFFFFFFFu, sz, lw);
        far = wbi;
    }
}

// ---------------- ball query 1: 16 centroids x 8 point-splits ---------------
__global__ void __launch_bounds__(256) k_bq1c(const float* __restrict__ xyz) {
    int bid   = blockIdx.x;
    int b     = bid / (32 * SP1);
    int rem   = bid % (32 * SP1);
    int grp   = rem / SP1;
    int split = rem % SP1;
    int g0    = grp * G1;
    int t     = threadIdx.x;

    __shared__ float s_cx[G1], s_cy[G1], s_cz[G1], s_cn[G1];
    if (t < G1) {
        int s  = g0 + t;
        int fi = g_fps1[b * NP1 + s];
        s_cx[t] = g_nx1[(b * NP1 + s) * 3 + 0];
        s_cy[t] = g_nx1[(b * NP1 + s) * 3 + 1];
        s_cz[t] = g_nx1[(b * NP1 + s) * 3 + 2];
        s_cn[t] = g_norms1[b * N1 + fi];
    }
    __syncthreads();

    float cxr[G1], cyr[G1], czr[G1], cnr[G1];
#pragma unroll
    for (int g = 0; g < G1; ++g) {
        cxr[g] = s_cx[g]; cyr[g] = s_cy[g]; czr[g] = s_cz[g]; cnr[g] = s_cn[g];
    }

    const float* X  = xyz + (size_t)b * 6 * N1;
    const float* Y  = X + N1;
    const float* Z  = X + 2 * N1;
    const float* NN = g_norms1 + b * N1;
    const float r2  = (float)(0.025 * 0.025);
    int p0 = split * (N1 / SP1);

#pragma unroll 1
    for (int i = 0; i < (N1 / SP1) / 256; ++i) {
        int p = p0 + i * 256 + t;
        float x = X[p], y = Y[p], z = Z[p], nn = NN[p];
#pragma unroll
        for (int g = 0; g < G1; ++g) {
            float dot = cxr[g] * x + cyr[g] * y + czr[g] * z;
            float sq  = (cnr[g] + nn) - 2.0f * dot;   // mimic ref formula
            if (sq <= r2) {
                int cent = b * NP1 + g0 + g;
                int pos = atomicAdd(&g_ccnt1[cent], 1);
                if (pos < CCAP) g_coll1[cent * CCAP + pos] = p;
            }
        }
    }
}

// sort + truncate per centroid
__global__ void k_bqfix1() {
    int idx = blockIdx.x * 256 + threadIdx.x;
    if (idx >= B * NP1) return;
    int m = min(g_ccnt1[idx], CCAP);
    int buf[CCAP];
    for (int i = 0; i < m; ++i) buf[i] = g_coll1[idx * CCAP + i];
    for (int i = 1; i < m; ++i) {
        int key = buf[i], j = i - 1;
        while (j >= 0 && buf[j] > key) { buf[j + 1] = buf[j]; --j; }
        buf[j + 1] = key;
    }
    int K = min(m, NS1);
    if (K == 0) { buf[0] = g_fps1[idx]; K = 1; }
    g_cnt1[idx] = K;
    for (int i = 0; i < K; ++i) g_list1[idx * 64 + i] = buf[i];
}

// ---------------- ball query 2 ---------------------------------------------
__global__ void __launch_bounds__(128) k_bq2() {
    int b  = blockIdx.x >> 5;
    int g0 = (blockIdx.x & 31) * 8;
    int t  = threadIdx.x;
    __shared__ float s_cx[8], s_cy[8], s_cz[8], s_cn[8];
    __shared__ int   s_cnt[8];
    __shared__ int   s_buf[8][CAP];

    if (t < 8) {
        int s  = g0 + t;
        int fi = g_fps2[b * NP2 + s];
        s_cx[t] = g_nx2[(b * NP2 + s) * 3 + 0];
        s_cy[t] = g_nx2[(b * NP2 + s) * 3 + 1];
        s_cz[t] = g_nx2[(b * NP2 + s) * 3 + 2];
        s_cn[t] = g_norms2[b * N2 + fi];
        s_cnt[t] = 0;
    }
    __syncthreads();

    const float r2 = (float)(0.05 * 0.05);
    for (int p = t; p < N2; p += 128) {
        float x  = g_nx1[(b * N2 + p) * 3 + 0];
        float y  = g_nx1[(b * N2 + p) * 3 + 1];
        float z  = g_nx1[(b * N2 + p) * 3 + 2];
        float nn = g_norms2[b * N2 + p];
#pragma unroll
        for (int g = 0; g < 8; ++g) {
            float dot = s_cx[g] * x + s_cy[g] * y + s_cz[g] * z;
            float sq  = (s_cn[g] + nn) - 2.0f * dot;
            if (sq <= r2) {
                int pos = atomicAdd(&s_cnt[g], 1);
                if (pos < CAP) s_buf[g][pos] = p;
            }
        }
    }
    __syncthreads();

    if (t < 8) {
        int s = g0 + t;
        int m = min(s_cnt[t], CAP);
        int* bf = s_buf[t];
        for (int i = 1; i < m; ++i) {
            int key = bf[i], j = i - 1;
            while (j >= 0 && bf[j] > key) { bf[j + 1] = bf[j]; --j; }
            bf[j + 1] = key;
        }
        int K = min(m, NS2);
        if (K == 0) { bf[0] = g_fps2[b * NP2 + s]; K = 1; }
        g_cnt2[b * NP2 + s] = K;
        for (int i = 0; i < K; ++i) g_list2[(b * NP2 + s) * 64 + i] = bf[i];
    }
}

// ---------------- SA1 MLP (6->64->64->128) + max, distinct points only -----
__global__ void __launch_bounds__(128) k_mlp1(const float* __restrict__ xyz,
                                              const float* __restrict__ b1,
                                              const float* __restrict__ b2,
                                              const float* __restrict__ b3) {
    int bs = blockIdx.x;          // b*512 + s
    int b  = bs >> 9;
    int t  = threadIdx.x;
    __shared__ float s_f[6], s_h1[64], s_h2[64], s_c[3];
    if (t < 3) s_c[t] = g_nx1[bs * 3 + t];
    int K = g_cnt1[bs];
    float macc = -3.402823466e38f;
    __syncthreads();

    for (int k = 0; k < K; ++k) {
        int n = g_list1[bs * 64 + k];
        if (t < 6) {
            float v = xyz[((size_t)b * 6 + t) * N1 + n];
            if (t < 3) v -= s_c[t];
            s_f[t] = v;
        }
        __syncthreads();
        if (t < 64) {
            float a = b1[t];
#pragma unroll
            for (int c = 0; c < 6; ++c) a = fmaf(g_w1t[c * 64 + t], s_f[c], a);
            s_h1[t] = fmaxf(a, 0.0f);
        }
        __syncthreads();
        if (t < 64) {
            float a = b2[t];
#pragma unroll
            for (int c = 0; c < 64; ++c) a = fmaf(g_w2t[c * 64 + t], s_h1[c], a);
            s_h2[t] = fmaxf(a, 0.0f);
        }
        __syncthreads();
        {
            float a = b3[t];
#pragma unroll
            for (int c = 0; c < 64; ++c) a = fmaf(g_w3t[c * 128 + t], s_h2[c], a);
            macc = fmaxf(macc, fmaxf(a, 0.0f));
        }
        __syncthreads();
    }
    g_feat1[bs * 128 + t] = macc;
}

// ---------------- SA2 MLP (131->128->128->285) + max -----------------------
__global__ void __launch_bounds__(288) k_mlp2(const float* __restrict__ b1,
                                              const float* __restrict__ b2,
                                              const float* __restrict__ b3,
                                              float* __restrict__ out) {
    int bs = blockIdx.x;          // b*256 + s
    int b  = bs >> 8;
    int t  = threadIdx.x;
    __shared__ float s_f[131], s_h1[128], s_h2[128], s_c[3];
    if (t < 3) s_c[t] = g_nx2[bs * 3 + t];
    int K = g_cnt2[bs];
    float macc = -3.402823466e38f;
    __syncthreads();

    for (int k = 0; k < K; ++k) {
        int n = g_list2[bs * 64 + k];
        if (t < 131) {
            float v;
            if (t < 3) v = g_nx1[(b * N2 + n) * 3 + t] - s_c[t];
            else       v = g_feat1[(b * N2 + n) * 128 + (t - 3)];
            s_f[t] = v;
        }
        __syncthreads();
        if (t < 128) {
            float a = b1[t];
#pragma unroll
            for (int c = 0; c < 131; ++c) a = fmaf(g_w1t2[c * 128 + t], s_f[c], a);
            s_h1[t] = fmaxf(a, 0.0f);
        }
        __syncthreads();
        if (t < 128) {
            float a = b2[t];
#pragma unroll
            for (int c = 0; c < 128; ++c) a = fmaf(g_w2t2[c * 128 + t], s_h1[c], a);
            s_h2[t] = fmaxf(a, 0.0f);
        }
        __syncthreads();
        if (t < 285) {
            float a = b3[t];
#pragma unroll
            for (int c = 0; c < 128; ++c) a = fmaf(g_w3t2[c * 285 + t], s_h2[c], a);
            macc = fmaxf(macc, fmaxf(a, 0.0f));
        }
        __syncthreads();
    }
    if (t < 285) out[B * 3 * NP2 + bs * 285 + t] = macc;  // l2_points (B,256,285)
}

// ---------------- l2_xyz output: (B,3,256) ---------------------------------
__global__ void k_out_xyz(float* __restrict__ out) {
    int i = blockIdx.x * 256 + threadIdx.x;
    if (i < B * 3 * NP2) {
        int b = i / (3 * NP2);
        int r = i % (3 * NP2);
        int d = r / NP2;
        int s = r % NP2;
        out[i] = g_nx2[(b * NP2 + s) * 3 + d];
    }
}

// ---------------- launch ----------------------------------------------------
extern "C" void kernel_launch(void* const* d_in, const int* in_sizes, int n_in,
                              void* d_out, int out_size) {
    (void)in_sizes; (void)n_in; (void)out_size;
    const float* xyz = (const float*)d_in[0];
    const float* w1  = (const float*)d_in[1];  const float* bb1 = (const float*)d_in[2];
    const float* w2  = (const float*)d_in[3];  const float* bb2 = (const float*)d_in[4];
    const float* w3  = (const float*)d_in[5];  const float* bb3 = (const float*)d_in[6];
    const float* u1  = (const float*)d_in[7];  const float* cc1 = (const float*)d_in[8];
    const float* u2  = (const float*)d_in[9];  const float* cc2 = (const float*)d_in[10];
    const float* u3  = (const float*)d_in[11]; const float* cc3 = (const float*)d_in[12];
    float* out = (float*)d_out;

    k_transpose_all<<<(82304 + B * NP1 + 255) / 256, 256>>>(w1, w2, w3, u1, u2, u3);
    k_norms1<<<(B * N1) / 256, 256>>>(xyz);
    k_fps1<<<B * FCL, 512>>>(xyz);
    k_bq1c<<<B * 32 * SP1, 256>>>(xyz);
    k_bqfix1<<<(B * NP1 + 255) / 256, 256>>>();
    k_mlp1<<<B * NP1, 128>>>(xyz, bb1, bb2, bb3);
    k_norms2<<<(B * N2 + 255) / 256, 256>>>();
    k_fps2<<<B, 32>>>();
    k_bq2<<<B * 32, 128>>>();
    k_mlp2<<<B * NP2, 288>>>(cc1, cc2, cc3, out);
    k_out_xyz<<<(B * 3 * NP2 + 255) / 256, 256>>>(out);
}